// round 3
// baseline (speedup 1.0000x reference)
#include <cuda_runtime.h>
#include <cstdint>

typedef unsigned long long ull;

// Fixed problem shapes
#define KCODES   1024
#define DIM      64
#define SPATIAL  16384            // L*H*W
#define NVEC     65536            // B * SPATIAL
#define QELEMS   4194304          // B * C * SPATIAL
#define TILE     128              // codes per smem tile
#define NTILES   (KCODES / TILE)
#define VTHREADS 64
#define VBLOCKS  (NVEC / VTHREADS)   // 1024

// loss-emulation chunking
#define NCHUNK   1024
#define CHUNK    4096             // elements per chunk (1024 per lane)
#define WLANES   4                // NEON fp32 lanes on aarch64 host

// d_out layout (float32): [quantized QELEMS][loss][indices NVEC]
#define LOSS_OFF QELEMS
#define IDX_OFF  (QELEMS + 1)

__device__ float  g_cbn[KCODES];
__device__ float  g_v[QELEMS];             // per-element fp32 (q-x)^2, linear [B,C,L,H,W] order
__device__ double g_chunk[NCHUNK][WLANES]; // per-chunk per-lane exact sums
__device__ double g_pref[NCHUNK][WLANES];  // lane prefix before chunk
__device__ double g_lanetot[WLANES];
__device__ double g_corr[NCHUNK][WLANES];  // per-chunk per-lane rounding corrections

__device__ __forceinline__ ull pack2(float lo, float hi) {
    return (ull)__float_as_uint(lo) | ((ull)__float_as_uint(hi) << 32);
}

// ||cb_k||^2, sequential fp32 (matches reference numerics)
__global__ void prep_kernel(const float* __restrict__ cb) {
    int k = blockIdx.x * blockDim.x + threadIdx.x;
    if (k >= KCODES) return;
    float a = 0.f;
#pragma unroll
    for (int c = 0; c < DIM; c++) {
        float v = cb[k * DIM + c];
        a = __fadd_rn(a, __fmul_rn(v, v));
    }
    g_cbn[k] = a;
}

__global__ __launch_bounds__(VTHREADS) void vq_kernel(
    const float* __restrict__ in,
    const float* __restrict__ cb,
    float* __restrict__ out)
{
    // interleaved code-pair tile: s_pk[pair][j] = ulonglong2 covering k-indices 2j,2j+1
    // low 32 bits = code 2p (lane0), high 32 = code 2p+1 (lane1)
    __shared__ ulonglong2 s_pk[ (TILE/2) * (DIM/2) ];   // 64*32*16B = 32 KB
    __shared__ float      s_cbn[TILE];

    const int tid = threadIdx.x;
    const int n   = blockIdx.x * VTHREADS + tid;
    const int b   = n >> 14;           // / SPATIAL
    const int sp  = n & (SPATIAL - 1);
    const float* xb = in + (size_t)b * DIM * SPATIAL + sp;

    // load x, compute A sequentially (bit-exact vs reference), build packed (x,x)
    float A = 0.f;
    ull xp[DIM];
#pragma unroll
    for (int c = 0; c < DIM; c++) {
        float xv = xb[(size_t)c * SPATIAL];
        A = __fadd_rn(A, __fmul_rn(xv, xv));
        xp[c] = pack2(xv, xv);
    }

    float best  = 3.402823466e38f;
    int   bestk = 0;

    for (int t = 0; t < NTILES; t++) {
        __syncthreads();
        // build interleaved tile
        for (int idx = tid; idx < (TILE/2) * DIM; idx += VTHREADS) {
            int pair = idx >> 6;        // 0..63
            int i    = idx & 63;        // k index
            const float* g = cb + ((size_t)(t * TILE + 2 * pair) * DIM + i);
            reinterpret_cast<ull*>(s_pk)[pair * DIM + i] = pack2(g[0], g[DIM]);
        }
        for (int i = tid; i < TILE; i += VTHREADS) s_cbn[i] = g_cbn[t * TILE + i];
        __syncthreads();

#pragma unroll 2
        for (int p = 0; p < TILE / 2; p++) {
            const ulonglong2* row = s_pk + p * (DIM / 2);
            ull acc = 0ull;   // (+0.0f, +0.0f)
#pragma unroll
            for (int j = 0; j < DIM / 2; j++) {
                ulonglong2 c2 = row[j];
                asm("fma.rn.f32x2 %0, %1, %2, %0;" : "+l"(acc) : "l"(c2.x), "l"(xp[2 * j]));
                asm("fma.rn.f32x2 %0, %1, %2, %0;" : "+l"(acc) : "l"(c2.y), "l"(xp[2 * j + 1]));
            }
            float dA = __uint_as_float((unsigned)(acc & 0xffffffffull));
            float dB = __uint_as_float((unsigned)(acc >> 32));
            float d2A = __fadd_rn(__fsub_rn(A, __fmul_rn(2.0f, dA)), s_cbn[2 * p]);
            if (d2A < best) { best = d2A; bestk = t * TILE + 2 * p; }
            float d2B = __fadd_rn(__fsub_rn(A, __fmul_rn(2.0f, dB)), s_cbn[2 * p + 1]);
            if (d2B < best) { best = d2B; bestk = t * TILE + 2 * p + 1; }
        }
    }

    out[IDX_OFF + n] = (float)bestk;

    // gather, write quantized_st (== x + (q-x)), store v = (q-x)^2 in linear order
    const float* crow = cb + (size_t)bestk * DIM;
#pragma unroll
    for (int c = 0; c < DIM; c++) {
        float q  = crow[c];
        float xv = xb[(size_t)c * SPATIAL];
        float df = __fsub_rn(q, xv);
        size_t off = ((size_t)(b * DIM + c)) * SPATIAL + sp;
        out[off] = __fadd_rn(xv, df);
        g_v[off] = __fmul_rn(df, df);
    }
}

// per-chunk per-lane exact (double) sums
__global__ void chunk_kernel() {
    __shared__ double s[256];
    int c = blockIdx.x, tid = threadIdx.x;
    double acc = 0.0;
#pragma unroll
    for (int k = 0; k < CHUNK / 256; k++)
        acc += (double)g_v[(size_t)c * CHUNK + tid + k * 256];
    s[tid] = acc;
    __syncthreads();
#pragma unroll
    for (int off = 128; off >= WLANES; off >>= 1) {
        if (tid < off) s[tid] += s[tid + off];
        __syncthreads();
    }
    if (tid < WLANES) g_chunk[c][tid] = s[tid];
}

// sequential lane prefixes across chunks
__global__ void prefix_kernel() {
    int l = threadIdx.x;
    if (l >= WLANES) return;
    double run = 0.0;
    for (int c = 0; c < NCHUNK; c++) {
        g_pref[c][l] = run;
        run += g_chunk[c][l];
    }
    g_lanetot[l] = run;
}

// per-element fp32 rounding correction: round_u(v) - v with u = ulp(prefix + v)
__global__ void corr_kernel() {
    __shared__ double s[256];
    int c = blockIdx.x, tid = threadIdx.x;
    int lane = tid & (WLANES - 1);
    double base = g_pref[c][lane];
    double avg  = g_chunk[c][lane] * (1.0 / (CHUNK / WLANES));
    double acc = 0.0;
#pragma unroll
    for (int k = 0; k < CHUNK / 256; k++) {
        int i = tid + k * 256;
        double v = (double)g_v[(size_t)c * CHUNK + i];
        double Sest = base + (double)(i >> 2) * avg;   // prefix before this element
        double w = Sest + v;
        if (w > 0.0 && v > 0.0) {
            int e;
            frexp(w, &e);                 // w in [2^(e-1), 2^e)
            double u = ldexp(1.0, e - 24);  // fp32 ulp of that binade
            acc += rint(v / u) * u - v;
        }
    }
    s[tid] = acc;
    __syncthreads();
#pragma unroll
    for (int off = 128; off >= WLANES; off >>= 1) {
        if (tid < off) s[tid] += s[tid + off];
        __syncthreads();
    }
    if (tid < WLANES) g_corr[c][tid] = s[tid];
}

__global__ void final_kernel(float* __restrict__ out) {
    __shared__ float lf[WLANES];
    int l = threadIdx.x;
    if (l < WLANES) {
        double cs = 0.0;
        for (int c = 0; c < NCHUNK; c++) cs += g_corr[c][l];
        lf[l] = (float)(g_lanetot[l] + cs);   // emulated fp32 lane sum
    }
    __syncthreads();
    if (l == 0) {
        // LLVM-style vector reduce of 4 lanes: halves then combine
        float s = __fadd_rn(__fadd_rn(lf[0], lf[2]), __fadd_rn(lf[1], lf[3]));
        float m = s * (1.0f / (float)QELEMS);              // exact (power of 2)
        out[LOSS_OFF] = __fadd_rn(m, __fmul_rn(0.25f, m)); // q_loss + 0.25*e_loss
    }
}

extern "C" void kernel_launch(void* const* d_in, const int* in_sizes, int n_in,
                              void* d_out, int out_size) {
    const float* in = (const float*)d_in[0];   // [4,64,16,32,32]
    const float* cb = (const float*)d_in[1];   // [1024,64]
    float* out = (float*)d_out;

    prep_kernel<<<4, 256>>>(cb);
    vq_kernel<<<VBLOCKS, VTHREADS>>>(in, cb, out);
    chunk_kernel<<<NCHUNK, 256>>>();
    prefix_kernel<<<1, 32>>>();
    corr_kernel<<<NCHUNK, 256>>>();
    final_kernel<<<1, 32>>>(out);
}

// round 4
// speedup vs baseline: 1.5221x; 1.5221x over previous
#include <cuda_runtime.h>
#include <cstdint>

typedef unsigned long long ull;

// Fixed problem shapes
#define KCODES   1024
#define DIM      64
#define SPATIAL  16384
#define NVEC     65536
#define QELEMS   4194304
#define TILE     128
#define NTILES   (KCODES / TILE)
#define VTHREADS 64
#define VBLOCKS  (NVEC / VTHREADS)

// loss-emulation chunking
#define NCHUNK   1024
#define CHUNK    4096             // elements per chunk (1024 per lane)
#define WLANES   4                // NEON fp32 lanes on aarch64 host

// d_out layout (float32): [quantized QELEMS][loss][indices NVEC]
#define LOSS_OFF QELEMS
#define IDX_OFF  (QELEMS + 1)

__device__ float  g_cbn[KCODES];
__device__ float  g_v[QELEMS];              // per-element fp32 (q-x)^2, linear order
__device__ double g_chunk[NCHUNK * WLANES]; // per-chunk per-lane exact sums [c*4+l]
__device__ double g_pref[NCHUNK * WLANES];  // lane prefix before chunk
__device__ double g_lanetot[WLANES];
__device__ double g_corr[NCHUNK * WLANES];  // per-chunk per-lane rounding corrections

__device__ __forceinline__ ull pack2(float lo, float hi) {
    return (ull)__float_as_uint(lo) | ((ull)__float_as_uint(hi) << 32);
}

// fp32-ulp of the binade containing positive double w (w in [2^(e-1),2^e) -> 2^(e-24))
__device__ __forceinline__ double f32_ulp_of(double w) {
    int E = (int)((__double_as_longlong(w) >> 52) & 0x7ff);   // biased exponent
    return __longlong_as_double((long long)(E - 23) << 52);   // 2^(E-1023-23)
}

__global__ void prep_kernel(const float* __restrict__ cb) {
    int k = blockIdx.x * blockDim.x + threadIdx.x;
    if (k >= KCODES) return;
    float a = 0.f;
#pragma unroll
    for (int c = 0; c < DIM; c++) {
        float v = cb[k * DIM + c];
        a = __fadd_rn(a, __fmul_rn(v, v));
    }
    g_cbn[k] = a;
}

__global__ __launch_bounds__(VTHREADS) void vq_kernel(
    const float* __restrict__ in,
    const float* __restrict__ cb,
    float* __restrict__ out)
{
    __shared__ ulonglong2 s_pk[(TILE / 2) * (DIM / 2)];   // 32 KB
    __shared__ float      s_cbn[TILE];

    const int tid = threadIdx.x;
    const int n   = blockIdx.x * VTHREADS + tid;
    const int b   = n >> 14;
    const int sp  = n & (SPATIAL - 1);
    const float* xb = in + (size_t)b * DIM * SPATIAL + sp;

    float A = 0.f;
    ull xp[DIM];
#pragma unroll
    for (int c = 0; c < DIM; c++) {
        float xv = xb[(size_t)c * SPATIAL];
        A = __fadd_rn(A, __fmul_rn(xv, xv));
        xp[c] = pack2(xv, xv);
    }

    float best  = 3.402823466e38f;
    int   bestk = 0;

    for (int t = 0; t < NTILES; t++) {
        __syncthreads();
        for (int idx = tid; idx < (TILE / 2) * DIM; idx += VTHREADS) {
            int pair = idx >> 6;
            int i    = idx & 63;
            const float* g = cb + ((size_t)(t * TILE + 2 * pair) * DIM + i);
            reinterpret_cast<ull*>(s_pk)[pair * DIM + i] = pack2(g[0], g[DIM]);
        }
        for (int i = tid; i < TILE; i += VTHREADS) s_cbn[i] = g_cbn[t * TILE + i];
        __syncthreads();

#pragma unroll 2
        for (int p = 0; p < TILE / 2; p++) {
            const ulonglong2* row = s_pk + p * (DIM / 2);
            ull acc = 0ull;
#pragma unroll
            for (int j = 0; j < DIM / 2; j++) {
                ulonglong2 c2 = row[j];
                asm("fma.rn.f32x2 %0, %1, %2, %0;" : "+l"(acc) : "l"(c2.x), "l"(xp[2 * j]));
                asm("fma.rn.f32x2 %0, %1, %2, %0;" : "+l"(acc) : "l"(c2.y), "l"(xp[2 * j + 1]));
            }
            float dA = __uint_as_float((unsigned)(acc & 0xffffffffull));
            float dB = __uint_as_float((unsigned)(acc >> 32));
            float d2A = __fadd_rn(__fsub_rn(A, __fmul_rn(2.0f, dA)), s_cbn[2 * p]);
            if (d2A < best) { best = d2A; bestk = t * TILE + 2 * p; }
            float d2B = __fadd_rn(__fsub_rn(A, __fmul_rn(2.0f, dB)), s_cbn[2 * p + 1]);
            if (d2B < best) { best = d2B; bestk = t * TILE + 2 * p + 1; }
        }
    }

    out[IDX_OFF + n] = (float)bestk;

    const float* crow = cb + (size_t)bestk * DIM;
#pragma unroll
    for (int c = 0; c < DIM; c++) {
        float q  = crow[c];
        float xv = xb[(size_t)c * SPATIAL];
        float df = __fsub_rn(q, xv);
        size_t off = ((size_t)(b * DIM + c)) * SPATIAL + sp;
        out[off] = __fadd_rn(xv, df);
        g_v[off] = __fmul_rn(df, df);
    }
}

// per-chunk per-lane exact (double) sums; mod-4 class preserved through the tree
__global__ void chunk_kernel() {
    __shared__ double s[256];
    int c = blockIdx.x, tid = threadIdx.x;
    double acc = 0.0;
#pragma unroll
    for (int k = 0; k < CHUNK / 256; k++)
        acc += (double)g_v[(size_t)c * CHUNK + tid + k * 256];
    s[tid] = acc;
    __syncthreads();
#pragma unroll
    for (int off = 128; off >= WLANES; off >>= 1) {
        if (tid < off) s[tid] += s[tid + off];
        __syncthreads();
    }
    if (tid < WLANES) g_chunk[c * WLANES + tid] = s[tid];
}

// parallel per-lane exclusive scan over 1024 chunks (Kogge-Stone in smem)
__global__ __launch_bounds__(1024) void prefix_kernel() {
    __shared__ double s[WLANES][NCHUNK];   // 32 KB
    int t = threadIdx.x;
#pragma unroll
    for (int l = 0; l < WLANES; l++) s[l][t] = g_chunk[t * WLANES + l];
    __syncthreads();
    for (int off = 1; off < NCHUNK; off <<= 1) {
        double tmp[WLANES];
#pragma unroll
        for (int l = 0; l < WLANES; l++) tmp[l] = (t >= off) ? s[l][t - off] : 0.0;
        __syncthreads();
#pragma unroll
        for (int l = 0; l < WLANES; l++) s[l][t] += tmp[l];
        __syncthreads();
    }
#pragma unroll
    for (int l = 0; l < WLANES; l++) {
        g_pref[t * WLANES + l] = (t > 0) ? s[l][t - 1] : 0.0;   // exclusive
        if (t == NCHUNK - 1) g_lanetot[l] = s[l][t];
    }
}

// per-element fp32 rounding correction with EXACT double in-chunk prefixes.
// thread layout: lane = tid&3, strip = tid>>2 (64 strips/lane, 16 elems/strip)
__global__ void corr_kernel() {
    __shared__ double sp[256];   // strip sums / prefixes, index = strip*4+lane
    int c = blockIdx.x, tid = threadIdx.x;
    int lane  = tid & 3;
    int strip = tid >> 2;
    const float* vbase = g_v + (size_t)c * CHUNK + lane;

    // pass 1: strip sums (elements strip*16+j, j=0..15, stride 4 in memory)
    double ssum = 0.0;
#pragma unroll
    for (int j = 0; j < 16; j++)
        ssum += (double)vbase[(size_t)(strip * 16 + j) * 4];
    sp[tid] = ssum;
    __syncthreads();

    // exclusive Kogge-Stone over strips (per lane)
#pragma unroll
    for (int off = 1; off < 64; off <<= 1) {
        double tmp = (strip >= off) ? sp[(strip - off) * 4 + lane] : 0.0;
        __syncthreads();
        sp[tid] += tmp;
        __syncthreads();
    }
    double run = g_pref[c * WLANES + lane] + ((strip > 0) ? sp[(strip - 1) * 4 + lane] : 0.0);
    __syncthreads();

    // pass 2: exact running prefix, per-element correction
    double acc = 0.0;
#pragma unroll
    for (int j = 0; j < 16; j++) {
        double v = (double)vbase[(size_t)(strip * 16 + j) * 4];
        double w = run + v;
        if (v > 0.0 && w > 0.0) {
            double u = f32_ulp_of(w);
            acc += rint(v / u) * u - v;
        }
        run += v;
    }

    // reduce corrections over strips per lane
    sp[tid] = acc;
    __syncthreads();
#pragma unroll
    for (int off = 32; off > 0; off >>= 1) {
        if (strip < off) sp[tid] += sp[tid + off * 4];
        __syncthreads();
    }
    if (strip == 0) g_corr[c * WLANES + lane] = sp[lane];
}

__global__ __launch_bounds__(1024) void final_kernel(float* __restrict__ out) {
    __shared__ double s[WLANES][NCHUNK];   // 32 KB
    __shared__ float  lf[WLANES];
    int t = threadIdx.x;
#pragma unroll
    for (int l = 0; l < WLANES; l++) s[l][t] = g_corr[t * WLANES + l];
    __syncthreads();
#pragma unroll
    for (int off = 512; off > 0; off >>= 1) {
        if (t < off) {
#pragma unroll
            for (int l = 0; l < WLANES; l++) s[l][t] += s[l][t + off];
        }
        __syncthreads();
    }
    if (t < WLANES) lf[t] = (float)(g_lanetot[t] + s[t][0]);  // emulated fp32 lane sum
    __syncthreads();
    if (t == 0) {
        // NEON pairwise reduce: (0+2)+(1+3)
        float sum = __fadd_rn(__fadd_rn(lf[0], lf[2]), __fadd_rn(lf[1], lf[3]));
        float m = sum * (1.0f / (float)QELEMS);             // exact scale (pow2)
        out[LOSS_OFF] = __fadd_rn(m, __fmul_rn(0.25f, m));  // q_loss + 0.25*e_loss
    }
}

extern "C" void kernel_launch(void* const* d_in, const int* in_sizes, int n_in,
                              void* d_out, int out_size) {
    const float* in = (const float*)d_in[0];
    const float* cb = (const float*)d_in[1];
    float* out = (float*)d_out;

    prep_kernel<<<4, 256>>>(cb);
    vq_kernel<<<VBLOCKS, VTHREADS>>>(in, cb, out);
    chunk_kernel<<<NCHUNK, 256>>>();
    prefix_kernel<<<1, 1024>>>();
    corr_kernel<<<NCHUNK, 256>>>();
    final_kernel<<<1, 1024>>>(out);
}

// round 6
// speedup vs baseline: 1.9538x; 1.2836x over previous
#include <cuda_runtime.h>
#include <cuda_bf16.h>
#include <cstdint>

// Fixed problem shapes
#define KCODES   1024
#define DIM      64
#define SPATIAL  16384
#define NVEC     65536
#define QELEMS   4194304

// loss-emulation chunking
#define NCHUNK   1024
#define CHUNK    4096
#define WLANES   4

// d_out layout (float32): [quantized QELEMS][loss][indices NVEC]
#define LOSS_OFF QELEMS
#define IDX_OFF  (QELEMS + 1)

// screening config
#define MROWS    128          // rows per CTA
#define NB       128          // codes per smem chunk
#define NCHUNKS_B (KCODES / NB)
#define WIN      8e-5f
#define CCAP     48           // candidate slots per row

// smem layout (bytes); A/B rows padded to 72 bf16 (144B) for conflict-free frags
#define PITCH    144
#define SA_HI    0
#define SA_LO    (SA_HI + MROWS * PITCH)          // 18432
#define SB_HI    (SA_LO + MROWS * PITCH)          // 36864
#define SB_LO    (SB_HI + NB * PITCH)             // 55296
#define S_CBN    (SB_LO + NB * PITCH)             // 73728
#define S_THR    (S_CBN + NB * 4)                 // 74240
#define S_CNT    (S_THR + MROWS * 4)              // 74752
#define S_CIDX   (S_CNT + MROWS * 4)              // 75264
#define S_CP     (S_CIDX + MROWS * CCAP * 2)      // 87552
#define SMEM_TOTAL (S_CP + MROWS * CCAP * 4)      // 112128

__device__ float  g_cbn[KCODES];
__device__ __align__(16) __nv_bfloat16 g_cb_hi[KCODES * DIM];
__device__ __align__(16) __nv_bfloat16 g_cb_lo[KCODES * DIM];
__device__ float  g_v[QELEMS];
__device__ double g_chunk[NCHUNK * WLANES];
__device__ double g_pref[NCHUNK * WLANES];
__device__ double g_lanetot[WLANES];
__device__ double g_corr[NCHUNK * WLANES];

__device__ __forceinline__ void mma16816(float* c, const uint32_t* a,
                                         uint32_t b0, uint32_t b1) {
    asm volatile(
        "mma.sync.aligned.m16n8k16.row.col.f32.bf16.bf16.f32 "
        "{%0,%1,%2,%3}, {%4,%5,%6,%7}, {%8,%9}, {%0,%1,%2,%3};"
        : "+f"(c[0]), "+f"(c[1]), "+f"(c[2]), "+f"(c[3])
        : "r"(a[0]), "r"(a[1]), "r"(a[2]), "r"(a[3]), "r"(b0), "r"(b1));
}

__device__ __forceinline__ double f32_ulp_of(double w) {
    int E = (int)((__double_as_longlong(w) >> 52) & 0x7ff);
    return __longlong_as_double((long long)(E - 23) << 52);
}

// ---------------- prep: cbn chain + bf16 hi/lo split ----------------
__global__ void prep_kernel(const float* __restrict__ cb) {
    int k = blockIdx.x * blockDim.x + threadIdx.x;
    if (k >= KCODES) return;
    float a = 0.f;
#pragma unroll
    for (int c = 0; c < DIM; c++) {
        float v = cb[k * DIM + c];
        a = __fadd_rn(a, __fmul_rn(v, v));
        __nv_bfloat16 h = __float2bfloat16_rn(v);
        __nv_bfloat16 l = __float2bfloat16_rn(__fsub_rn(v, __bfloat162float(h)));
        g_cb_hi[k * DIM + c] = h;
        g_cb_lo[k * DIM + c] = l;
    }
    g_cbn[k] = a;
}

// ---------------- main: warp-MMA split-bf16 screen + exact recheck ----------------
__global__ __launch_bounds__(MROWS, 2)
void vq3_kernel(const float* __restrict__ in,
                const float* __restrict__ cb,
                float* __restrict__ out)
{
    extern __shared__ char sm[];
    __nv_bfloat16* sAhi = (__nv_bfloat16*)(sm + SA_HI);
    __nv_bfloat16* sAlo = (__nv_bfloat16*)(sm + SA_LO);
    float*  sCbn = (float*)(sm + S_CBN);
    float*  sThr = (float*)(sm + S_THR);
    int*    sCnt = (int*)(sm + S_CNT);
    unsigned short* sCi = (unsigned short*)(sm + S_CIDX);
    float*  sCp  = (float*)(sm + S_CP);

    const int tid  = threadIdx.x;
    const int lane = tid & 31;
    const int g    = lane >> 2;        // 0..7
    const int t4   = lane & 3;         // 0..3
    const int wbase = (tid >> 5) * 32; // warp's row base

    const int n  = blockIdx.x * MROWS + tid;
    const int b  = n >> 14;
    const int sp = n & (SPATIAL - 1);
    const float* xb = in + (size_t)b * DIM * SPATIAL + sp;

    // ---- stage A: split x row into smem hi/lo tiles; zero counters ----
    sCnt[tid] = 0;
    {
        char* rh = sm + SA_HI + tid * PITCH;
        char* rl = sm + SA_LO + tid * PITCH;
#pragma unroll
        for (int c = 0; c < DIM; c += 2) {
            float x0 = xb[(size_t)c * SPATIAL];
            float x1 = xb[(size_t)(c + 1) * SPATIAL];
            __nv_bfloat16 h0 = __float2bfloat16_rn(x0);
            __nv_bfloat16 h1 = __float2bfloat16_rn(x1);
            __nv_bfloat16 l0 = __float2bfloat16_rn(__fsub_rn(x0, __bfloat162float(h0)));
            __nv_bfloat16 l1 = __float2bfloat16_rn(__fsub_rn(x1, __bfloat162float(h1)));
            *(uint32_t*)(rh + c * 2) =
                (uint32_t)__bfloat16_as_ushort(h0) | ((uint32_t)__bfloat16_as_ushort(h1) << 16);
            *(uint32_t*)(rl + c * 2) =
                (uint32_t)__bfloat16_as_ushort(l0) | ((uint32_t)__bfloat16_as_ushort(l1) << 16);
        }
    }
    __syncthreads();

    // ---- preload A-hi fragments (persist whole kernel): ahi[mt][ks][4] ----
    uint32_t ahi[2][4][4];
#pragma unroll
    for (int mt = 0; mt < 2; mt++) {
        int r0 = wbase + mt * 16 + g;
#pragma unroll
        for (int ks = 0; ks < 4; ks++) {
            int col = ks * 16 + t4 * 2;
            ahi[mt][ks][0] = *(uint32_t*)(sm + SA_HI + r0 * PITCH + col * 2);
            ahi[mt][ks][1] = *(uint32_t*)(sm + SA_HI + (r0 + 8) * PITCH + col * 2);
            ahi[mt][ks][2] = *(uint32_t*)(sm + SA_HI + r0 * PITCH + (col + 8) * 2);
            ahi[mt][ks][3] = *(uint32_t*)(sm + SA_HI + (r0 + 8) * PITCH + (col + 8) * 2);
        }
    }

    float rm[4] = {3.4e38f, 3.4e38f, 3.4e38f, 3.4e38f};   // rows g, g+8, g+16, g+24 (warp-local)

#define PUSH(ri, kidx, pv) do { \
        if ((pv) < rm[ri]) rm[ri] = (pv); \
        if ((pv) <= rm[ri] + WIN) { \
            int _r = wbase + (ri) * 8 + g; \
            int _s = atomicAdd(&sCnt[_r], 1); \
            if (_s < CCAP) { sCi[_r * CCAP + _s] = (unsigned short)(kidx); \
                             sCp[_r * CCAP + _s] = (pv); } \
        } \
    } while (0)

    for (int ch = 0; ch < NCHUNKS_B; ch++) {
        __syncthreads();   // prior chunk's B reads complete
        // load B chunk (128 codes) hi/lo + cbn slice; thread -> one code row
        {
            const uint4* gh = (const uint4*)(g_cb_hi + (size_t)(ch * NB + tid) * DIM);
            const uint4* gl = (const uint4*)(g_cb_lo + (size_t)(ch * NB + tid) * DIM);
            uint4* dh = (uint4*)(sm + SB_HI + tid * PITCH);
            uint4* dl = (uint4*)(sm + SB_LO + tid * PITCH);
#pragma unroll
            for (int u = 0; u < 8; u++) { dh[u] = gh[u]; dl[u] = gl[u]; }
            sCbn[tid] = g_cbn[ch * NB + tid];
        }
        __syncthreads();

        for (int ng = 0; ng < 4; ng++) {       // 4 groups of 4 n8-tiles
            float c[4][8];
#pragma unroll
            for (int i = 0; i < 4; i++)
#pragma unroll
                for (int j = 0; j < 8; j++) c[i][j] = 0.f;

#pragma unroll
            for (int ks = 0; ks < 4; ks++) {
                // A-lo fragments for this k-step
                uint32_t alo[2][4];
#pragma unroll
                for (int mt = 0; mt < 2; mt++) {
                    int r0 = wbase + mt * 16 + g;
                    int col = ks * 16 + t4 * 2;
                    alo[mt][0] = *(uint32_t*)(sm + SA_LO + r0 * PITCH + col * 2);
                    alo[mt][1] = *(uint32_t*)(sm + SA_LO + (r0 + 8) * PITCH + col * 2);
                    alo[mt][2] = *(uint32_t*)(sm + SA_LO + r0 * PITCH + (col + 8) * 2);
                    alo[mt][3] = *(uint32_t*)(sm + SA_LO + (r0 + 8) * PITCH + (col + 8) * 2);
                }
#pragma unroll
                for (int nt = 0; nt < 4; nt++) {
                    int nrow = (ng * 4 + nt) * 8 + g;     // B row (code) for this thread
                    int col  = ks * 16 + t4 * 2;
                    uint32_t bh0 = *(uint32_t*)(sm + SB_HI + nrow * PITCH + col * 2);
                    uint32_t bh1 = *(uint32_t*)(sm + SB_HI + nrow * PITCH + (col + 8) * 2);
                    mma16816(&c[nt][0], ahi[0][ks], bh0, bh1);
                    mma16816(&c[nt][4], ahi[1][ks], bh0, bh1);
                    mma16816(&c[nt][0], alo[0], bh0, bh1);
                    mma16816(&c[nt][4], alo[1], bh0, bh1);
                    uint32_t bl0 = *(uint32_t*)(sm + SB_LO + nrow * PITCH + col * 2);
                    uint32_t bl1 = *(uint32_t*)(sm + SB_LO + nrow * PITCH + (col + 8) * 2);
                    mma16816(&c[nt][0], ahi[0][ks], bl0, bl1);
                    mma16816(&c[nt][4], ahi[1][ks], bl0, bl1);
                }
            }

            // epilogue: p = cbn - 2*dot; running min + candidate push
#pragma unroll
            for (int nt = 0; nt < 4; nt++) {
                int nloc = (ng * 4 + nt) * 8 + t4 * 2;
                int kb   = ch * NB + nloc;
                float cb0 = sCbn[nloc], cb1 = sCbn[nloc + 1];
                float p;
                p = __fmaf_rn(-2.f, c[nt][0], cb0); PUSH(0, kb,     p);
                p = __fmaf_rn(-2.f, c[nt][1], cb1); PUSH(0, kb + 1, p);
                p = __fmaf_rn(-2.f, c[nt][2], cb0); PUSH(1, kb,     p);
                p = __fmaf_rn(-2.f, c[nt][3], cb1); PUSH(1, kb + 1, p);
                p = __fmaf_rn(-2.f, c[nt][4], cb0); PUSH(2, kb,     p);
                p = __fmaf_rn(-2.f, c[nt][5], cb1); PUSH(2, kb + 1, p);
                p = __fmaf_rn(-2.f, c[nt][6], cb0); PUSH(3, kb,     p);
                p = __fmaf_rn(-2.f, c[nt][7], cb1); PUSH(3, kb + 1, p);
            }
        }
    }
#undef PUSH

    // ---- reduce row minima across the 4 threads of each row-group ----
#pragma unroll
    for (int i = 0; i < 4; i++) {
        float m = rm[i];
        m = fminf(m, __shfl_xor_sync(0xffffffffu, m, 1));
        m = fminf(m, __shfl_xor_sync(0xffffffffu, m, 2));
        if (t4 == 0) sThr[wbase + i * 8 + g] = m + WIN;
    }
    __syncthreads();

    // ---- stage 2: exact recheck for row = tid ----
    float x[DIM];
    float A = 0.f;
#pragma unroll
    for (int c = 0; c < DIM; c++) {
        x[c] = xb[(size_t)c * SPATIAL];
        A = __fadd_rn(A, __fmul_rn(x[c], x[c]));
    }

    float best = 3.402823466e38f;
    int bestk = KCODES;
    const float thr = sThr[tid];
    const int cnt = sCnt[tid];

#define EVAL_K(kk) do { \
        const float4* cr = (const float4*)(cb + (size_t)(kk) * DIM); \
        float dot = 0.f; \
        _Pragma("unroll") \
        for (int i = 0; i < DIM / 4; i++) { \
            float4 c4 = cr[i]; \
            dot = __fmaf_rn(x[4 * i + 0], c4.x, dot); \
            dot = __fmaf_rn(x[4 * i + 1], c4.y, dot); \
            dot = __fmaf_rn(x[4 * i + 2], c4.z, dot); \
            dot = __fmaf_rn(x[4 * i + 3], c4.w, dot); \
        } \
        float d2 = __fadd_rn(__fsub_rn(A, __fmul_rn(2.0f, dot)), g_cbn[kk]); \
        if (d2 < best || (d2 == best && (kk) < bestk)) { best = d2; bestk = (kk); } \
    } while (0)

    if (cnt > CCAP) {
        for (int k = 0; k < KCODES; k++) EVAL_K(k);
    } else {
        for (int i = 0; i < cnt; i++) {
            if (sCp[tid * CCAP + i] <= thr) {
                int k = sCi[tid * CCAP + i];
                EVAL_K(k);
            }
        }
    }
#undef EVAL_K

    out[IDX_OFF + n] = (float)bestk;

    const float* crow = cb + (size_t)bestk * DIM;
#pragma unroll
    for (int c = 0; c < DIM; c++) {
        float q  = crow[c];
        float df = __fsub_rn(q, x[c]);
        size_t off = ((size_t)(b * DIM + c)) * SPATIAL + sp;
        out[off] = __fadd_rn(x[c], df);
        g_v[off] = __fmul_rn(df, df);
    }
}

// ---------------- loss emulation pipeline (proven) ----------------
__global__ void chunk_kernel() {
    __shared__ double s[256];
    int c = blockIdx.x, tid = threadIdx.x;
    double acc = 0.0;
#pragma unroll
    for (int k = 0; k < CHUNK / 256; k++)
        acc += (double)g_v[(size_t)c * CHUNK + tid + k * 256];
    s[tid] = acc;
    __syncthreads();
#pragma unroll
    for (int off = 128; off >= WLANES; off >>= 1) {
        if (tid < off) s[tid] += s[tid + off];
        __syncthreads();
    }
    if (tid < WLANES) g_chunk[c * WLANES + tid] = s[tid];
}

__global__ __launch_bounds__(1024) void prefix_kernel() {
    __shared__ double s[WLANES][NCHUNK];
    int t = threadIdx.x;
#pragma unroll
    for (int l = 0; l < WLANES; l++) s[l][t] = g_chunk[t * WLANES + l];
    __syncthreads();
    for (int off = 1; off < NCHUNK; off <<= 1) {
        double tmp[WLANES];
#pragma unroll
        for (int l = 0; l < WLANES; l++) tmp[l] = (t >= off) ? s[l][t - off] : 0.0;
        __syncthreads();
#pragma unroll
        for (int l = 0; l < WLANES; l++) s[l][t] += tmp[l];
        __syncthreads();
    }
#pragma unroll
    for (int l = 0; l < WLANES; l++) {
        g_pref[t * WLANES + l] = (t > 0) ? s[l][t - 1] : 0.0;
        if (t == NCHUNK - 1) g_lanetot[l] = s[l][t];
    }
}

__global__ void corr_kernel() {
    __shared__ double sp[256];
    int c = blockIdx.x, tid = threadIdx.x;
    int lane  = tid & 3;
    int strip = tid >> 2;
    const float* vbase = g_v + (size_t)c * CHUNK + lane;

    double ssum = 0.0;
#pragma unroll
    for (int j = 0; j < 16; j++)
        ssum += (double)vbase[(size_t)(strip * 16 + j) * 4];
    sp[tid] = ssum;
    __syncthreads();
#pragma unroll
    for (int off = 1; off < 64; off <<= 1) {
        double tmp = (strip >= off) ? sp[(strip - off) * 4 + lane] : 0.0;
        __syncthreads();
        sp[tid] += tmp;
        __syncthreads();
    }
    double run = g_pref[c * WLANES + lane] + ((strip > 0) ? sp[(strip - 1) * 4 + lane] : 0.0);
    __syncthreads();

    double acc = 0.0;
#pragma unroll
    for (int j = 0; j < 16; j++) {
        double v = (double)vbase[(size_t)(strip * 16 + j) * 4];
        double w = run + v;
        if (v > 0.0 && w > 0.0) {
            double u = f32_ulp_of(w);
            acc += rint(v / u) * u - v;
        }
        run += v;
    }

    sp[tid] = acc;
    __syncthreads();
#pragma unroll
    for (int off = 32; off > 0; off >>= 1) {
        if (strip < off) sp[tid] += sp[tid + off * 4];
        __syncthreads();
    }
    if (strip == 0) g_corr[c * WLANES + lane] = sp[lane];
}

__global__ __launch_bounds__(1024) void final_kernel(float* __restrict__ out) {
    __shared__ double s[WLANES][NCHUNK];
    __shared__ float  lf[WLANES];
    int t = threadIdx.x;
#pragma unroll
    for (int l = 0; l < WLANES; l++) s[l][t] = g_corr[t * WLANES + l];
    __syncthreads();
#pragma unroll
    for (int off = 512; off > 0; off >>= 1) {
        if (t < off) {
#pragma unroll
            for (int l = 0; l < WLANES; l++) s[l][t] += s[l][t + off];
        }
        __syncthreads();
    }
    if (t < WLANES) lf[t] = (float)(g_lanetot[t] + s[t][0]);
    __syncthreads();
    if (t == 0) {
        float sum = __fadd_rn(__fadd_rn(lf[0], lf[2]), __fadd_rn(lf[1], lf[3]));
        float m = sum * (1.0f / (float)QELEMS);
        out[LOSS_OFF] = __fadd_rn(m, __fmul_rn(0.25f, m));
    }
}

extern "C" void kernel_launch(void* const* d_in, const int* in_sizes, int n_in,
                              void* d_out, int out_size) {
    const float* in = (const float*)d_in[0];
    const float* cb = (const float*)d_in[1];
    float* out = (float*)d_out;

    cudaFuncSetAttribute(vq3_kernel, cudaFuncAttributeMaxDynamicSharedMemorySize, SMEM_TOTAL);

    prep_kernel<<<4, 256>>>(cb);
    vq3_kernel<<<NVEC / MROWS, MROWS, SMEM_TOTAL>>>(in, cb, out);
    chunk_kernel<<<NCHUNK, 256>>>();
    prefix_kernel<<<1, 1024>>>();
    corr_kernel<<<NCHUNK, 256>>>();
    final_kernel<<<1, 1024>>>(out);
}

// round 7
// speedup vs baseline: 1.9556x; 1.0009x over previous
#include <cuda_runtime.h>
#include <cuda_bf16.h>
#include <cstdint>

// Fixed problem shapes
#define KCODES   1024
#define DIM      64
#define SPATIAL  16384
#define NVEC     65536
#define QELEMS   4194304

// loss-emulation chunking
#define NCHUNK   1024
#define CHUNK    4096
#define WLANES   4

// d_out layout (float32): [quantized QELEMS][loss][indices NVEC]
#define LOSS_OFF QELEMS
#define IDX_OFF  (QELEMS + 1)

// screening config
#define MROWS    128          // rows per CTA
#define NB       128          // codes per smem chunk
#define NCHUNKS_B (KCODES / NB)
#define WIN      8e-5f
#define CCAP     48           // candidate slots per row

// smem layout (bytes); A/B rows padded to 72 bf16 (144B) for conflict-free frags
#define PITCH    144
#define SA_HI    0
#define SA_LO    (SA_HI + MROWS * PITCH)          // 18432
#define SB_HI    (SA_LO + MROWS * PITCH)          // 36864
#define SB_LO    (SB_HI + NB * PITCH)             // 55296
#define S_CBN    (SB_LO + NB * PITCH)             // 73728
#define S_THR    (S_CBN + NB * 4)                 // 74240
#define S_CNT    (S_THR + MROWS * 4)              // 74752
#define S_CIDX   (S_CNT + MROWS * 4)              // 75264
#define S_CP     (S_CIDX + MROWS * CCAP * 2)      // 87552
#define SMEM_TOTAL (S_CP + MROWS * CCAP * 4)      // 112128

__device__ float  g_cbn[KCODES];
__device__ __align__(16) __nv_bfloat16 g_cb_hi[KCODES * DIM];
__device__ __align__(16) __nv_bfloat16 g_cb_lo[KCODES * DIM];
__device__ float  g_v[QELEMS];
__device__ double g_chunk[NCHUNK * WLANES];
__device__ double g_pref[NCHUNK * WLANES];
__device__ double g_lanetot[WLANES];
__device__ double g_corr[NCHUNK * WLANES];

__device__ __forceinline__ void mma16816(float* c, const uint32_t* a,
                                         uint32_t b0, uint32_t b1) {
    asm volatile(
        "mma.sync.aligned.m16n8k16.row.col.f32.bf16.bf16.f32 "
        "{%0,%1,%2,%3}, {%4,%5,%6,%7}, {%8,%9}, {%0,%1,%2,%3};"
        : "+f"(c[0]), "+f"(c[1]), "+f"(c[2]), "+f"(c[3])
        : "r"(a[0]), "r"(a[1]), "r"(a[2]), "r"(a[3]), "r"(b0), "r"(b1));
}

__device__ __forceinline__ double f32_ulp_of(double w) {
    int E = (int)((__double_as_longlong(w) >> 52) & 0x7ff);
    return __longlong_as_double((long long)(E - 23) << 52);
}

// ---------------- prep: cbn chain + bf16 hi/lo split ----------------
__global__ void prep_kernel(const float* __restrict__ cb) {
    int k = blockIdx.x * blockDim.x + threadIdx.x;
    if (k >= KCODES) return;
    float a = 0.f;
#pragma unroll
    for (int c = 0; c < DIM; c++) {
        float v = cb[k * DIM + c];
        a = __fadd_rn(a, __fmul_rn(v, v));
        __nv_bfloat16 h = __float2bfloat16_rn(v);
        __nv_bfloat16 l = __float2bfloat16_rn(__fsub_rn(v, __bfloat162float(h)));
        g_cb_hi[k * DIM + c] = h;
        g_cb_lo[k * DIM + c] = l;
    }
    g_cbn[k] = a;
}

// ---------------- main: warp-MMA split-bf16 screen + exact recheck ----------------
__global__ __launch_bounds__(MROWS, 2)
void vq3_kernel(const float* __restrict__ in,
                const float* __restrict__ cb,
                float* __restrict__ out)
{
    extern __shared__ char sm[];
    __nv_bfloat16* sAhi = (__nv_bfloat16*)(sm + SA_HI);
    __nv_bfloat16* sAlo = (__nv_bfloat16*)(sm + SA_LO);
    float*  sCbn = (float*)(sm + S_CBN);
    float*  sThr = (float*)(sm + S_THR);
    int*    sCnt = (int*)(sm + S_CNT);
    unsigned short* sCi = (unsigned short*)(sm + S_CIDX);
    float*  sCp  = (float*)(sm + S_CP);

    const int tid  = threadIdx.x;
    const int lane = tid & 31;
    const int g    = lane >> 2;        // 0..7
    const int t4   = lane & 3;         // 0..3
    const int wbase = (tid >> 5) * 32; // warp's row base

    const int n  = blockIdx.x * MROWS + tid;
    const int b  = n >> 14;
    const int sp = n & (SPATIAL - 1);
    const float* xb = in + (size_t)b * DIM * SPATIAL + sp;

    // ---- stage A: split x row into smem hi/lo tiles; zero counters ----
    sCnt[tid] = 0;
    {
        char* rh = sm + SA_HI + tid * PITCH;
        char* rl = sm + SA_LO + tid * PITCH;
#pragma unroll
        for (int c = 0; c < DIM; c += 2) {
            float x0 = xb[(size_t)c * SPATIAL];
            float x1 = xb[(size_t)(c + 1) * SPATIAL];
            __nv_bfloat16 h0 = __float2bfloat16_rn(x0);
            __nv_bfloat16 h1 = __float2bfloat16_rn(x1);
            __nv_bfloat16 l0 = __float2bfloat16_rn(__fsub_rn(x0, __bfloat162float(h0)));
            __nv_bfloat16 l1 = __float2bfloat16_rn(__fsub_rn(x1, __bfloat162float(h1)));
            *(uint32_t*)(rh + c * 2) =
                (uint32_t)__bfloat16_as_ushort(h0) | ((uint32_t)__bfloat16_as_ushort(h1) << 16);
            *(uint32_t*)(rl + c * 2) =
                (uint32_t)__bfloat16_as_ushort(l0) | ((uint32_t)__bfloat16_as_ushort(l1) << 16);
        }
    }
    __syncthreads();

    // ---- preload A-hi fragments (persist whole kernel): ahi[mt][ks][4] ----
    uint32_t ahi[2][4][4];
#pragma unroll
    for (int mt = 0; mt < 2; mt++) {
        int r0 = wbase + mt * 16 + g;
#pragma unroll
        for (int ks = 0; ks < 4; ks++) {
            int col = ks * 16 + t4 * 2;
            ahi[mt][ks][0] = *(uint32_t*)(sm + SA_HI + r0 * PITCH + col * 2);
            ahi[mt][ks][1] = *(uint32_t*)(sm + SA_HI + (r0 + 8) * PITCH + col * 2);
            ahi[mt][ks][2] = *(uint32_t*)(sm + SA_HI + r0 * PITCH + (col + 8) * 2);
            ahi[mt][ks][3] = *(uint32_t*)(sm + SA_HI + (r0 + 8) * PITCH + (col + 8) * 2);
        }
    }

    float rm[4] = {3.4e38f, 3.4e38f, 3.4e38f, 3.4e38f};   // rows g, g+8, g+16, g+24 (warp-local)

#define PUSH(ri, kidx, pv) do { \
        if ((pv) < rm[ri]) rm[ri] = (pv); \
        if ((pv) <= rm[ri] + WIN) { \
            int _r = wbase + (ri) * 8 + g; \
            int _s = atomicAdd(&sCnt[_r], 1); \
            if (_s < CCAP) { sCi[_r * CCAP + _s] = (unsigned short)(kidx); \
                             sCp[_r * CCAP + _s] = (pv); } \
        } \
    } while (0)

    for (int ch = 0; ch < NCHUNKS_B; ch++) {
        __syncthreads();   // prior chunk's B reads complete
        // load B chunk (128 codes) hi/lo + cbn slice; thread -> one code row
        {
            const uint4* gh = (const uint4*)(g_cb_hi + (size_t)(ch * NB + tid) * DIM);
            const uint4* gl = (const uint4*)(g_cb_lo + (size_t)(ch * NB + tid) * DIM);
            uint4* dh = (uint4*)(sm + SB_HI + tid * PITCH);
            uint4* dl = (uint4*)(sm + SB_LO + tid * PITCH);
#pragma unroll
            for (int u = 0; u < 8; u++) { dh[u] = gh[u]; dl[u] = gl[u]; }
            sCbn[tid] = g_cbn[ch * NB + tid];
        }
        __syncthreads();

        for (int ng = 0; ng < 4; ng++) {       // 4 groups of 4 n8-tiles
            float c[4][8];
#pragma unroll
            for (int i = 0; i < 4; i++)
#pragma unroll
                for (int j = 0; j < 8; j++) c[i][j] = 0.f;

#pragma unroll
            for (int ks = 0; ks < 4; ks++) {
                // A-lo fragments for this k-step
                uint32_t alo[2][4];
#pragma unroll
                for (int mt = 0; mt < 2; mt++) {
                    int r0 = wbase + mt * 16 + g;
                    int col = ks * 16 + t4 * 2;
                    alo[mt][0] = *(uint32_t*)(sm + SA_LO + r0 * PITCH + col * 2);
                    alo[mt][1] = *(uint32_t*)(sm + SA_LO + (r0 + 8) * PITCH + col * 2);
                    alo[mt][2] = *(uint32_t*)(sm + SA_LO + r0 * PITCH + (col + 8) * 2);
                    alo[mt][3] = *(uint32_t*)(sm + SA_LO + (r0 + 8) * PITCH + (col + 8) * 2);
                }
#pragma unroll
                for (int nt = 0; nt < 4; nt++) {
                    int nrow = (ng * 4 + nt) * 8 + g;     // B row (code) for this thread
                    int col  = ks * 16 + t4 * 2;
                    uint32_t bh0 = *(uint32_t*)(sm + SB_HI + nrow * PITCH + col * 2);
                    uint32_t bh1 = *(uint32_t*)(sm + SB_HI + nrow * PITCH + (col + 8) * 2);
                    mma16816(&c[nt][0], ahi[0][ks], bh0, bh1);
                    mma16816(&c[nt][4], ahi[1][ks], bh0, bh1);
                    mma16816(&c[nt][0], alo[0], bh0, bh1);
                    mma16816(&c[nt][4], alo[1], bh0, bh1);
                    uint32_t bl0 = *(uint32_t*)(sm + SB_LO + nrow * PITCH + col * 2);
                    uint32_t bl1 = *(uint32_t*)(sm + SB_LO + nrow * PITCH + (col + 8) * 2);
                    mma16816(&c[nt][0], ahi[0][ks], bl0, bl1);
                    mma16816(&c[nt][4], ahi[1][ks], bl0, bl1);
                }
            }

            // epilogue: p = cbn - 2*dot; running min + candidate push
#pragma unroll
            for (int nt = 0; nt < 4; nt++) {
                int nloc = (ng * 4 + nt) * 8 + t4 * 2;
                int kb   = ch * NB + nloc;
                float cb0 = sCbn[nloc], cb1 = sCbn[nloc + 1];
                float p;
                p = __fmaf_rn(-2.f, c[nt][0], cb0); PUSH(0, kb,     p);
                p = __fmaf_rn(-2.f, c[nt][1], cb1); PUSH(0, kb + 1, p);
                p = __fmaf_rn(-2.f, c[nt][2], cb0); PUSH(1, kb,     p);
                p = __fmaf_rn(-2.f, c[nt][3], cb1); PUSH(1, kb + 1, p);
                p = __fmaf_rn(-2.f, c[nt][4], cb0); PUSH(2, kb,     p);
                p = __fmaf_rn(-2.f, c[nt][5], cb1); PUSH(2, kb + 1, p);
                p = __fmaf_rn(-2.f, c[nt][6], cb0); PUSH(3, kb,     p);
                p = __fmaf_rn(-2.f, c[nt][7], cb1); PUSH(3, kb + 1, p);
            }
        }
    }
#undef PUSH

    // ---- reduce row minima across the 4 threads of each row-group ----
#pragma unroll
    for (int i = 0; i < 4; i++) {
        float m = rm[i];
        m = fminf(m, __shfl_xor_sync(0xffffffffu, m, 1));
        m = fminf(m, __shfl_xor_sync(0xffffffffu, m, 2));
        if (t4 == 0) sThr[wbase + i * 8 + g] = m + WIN;
    }
    __syncthreads();

    // ---- stage 2: exact recheck for row = tid ----
    float x[DIM];
    float A = 0.f;
#pragma unroll
    for (int c = 0; c < DIM; c++) {
        x[c] = xb[(size_t)c * SPATIAL];
        A = __fadd_rn(A, __fmul_rn(x[c], x[c]));
    }

    float best = 3.402823466e38f;
    int bestk = KCODES;
    const float thr = sThr[tid];
    const int cnt = sCnt[tid];

#define EVAL_K(kk) do { \
        const float4* cr = (const float4*)(cb + (size_t)(kk) * DIM); \
        float dot = 0.f; \
        _Pragma("unroll") \
        for (int i = 0; i < DIM / 4; i++) { \
            float4 c4 = cr[i]; \
            dot = __fmaf_rn(x[4 * i + 0], c4.x, dot); \
            dot = __fmaf_rn(x[4 * i + 1], c4.y, dot); \
            dot = __fmaf_rn(x[4 * i + 2], c4.z, dot); \
            dot = __fmaf_rn(x[4 * i + 3], c4.w, dot); \
        } \
        float d2 = __fadd_rn(__fsub_rn(A, __fmul_rn(2.0f, dot)), g_cbn[kk]); \
        if (d2 < best || (d2 == best && (kk) < bestk)) { best = d2; bestk = (kk); } \
    } while (0)

    if (cnt > CCAP) {
        for (int k = 0; k < KCODES; k++) EVAL_K(k);
    } else {
        for (int i = 0; i < cnt; i++) {
            if (sCp[tid * CCAP + i] <= thr) {
                int k = sCi[tid * CCAP + i];
                EVAL_K(k);
            }
        }
    }
#undef EVAL_K

    out[IDX_OFF + n] = (float)bestk;

    const float* crow = cb + (size_t)bestk * DIM;
#pragma unroll
    for (int c = 0; c < DIM; c++) {
        float q  = crow[c];
        float df = __fsub_rn(q, x[c]);
        size_t off = ((size_t)(b * DIM + c)) * SPATIAL + sp;
        out[off] = __fadd_rn(x[c], df);
        g_v[off] = __fmul_rn(df, df);
    }
}

// ---------------- loss emulation pipeline (proven) ----------------
__global__ void chunk_kernel() {
    __shared__ double s[256];
    int c = blockIdx.x, tid = threadIdx.x;
    double acc = 0.0;
#pragma unroll
    for (int k = 0; k < CHUNK / 256; k++)
        acc += (double)g_v[(size_t)c * CHUNK + tid + k * 256];
    s[tid] = acc;
    __syncthreads();
#pragma unroll
    for (int off = 128; off >= WLANES; off >>= 1) {
        if (tid < off) s[tid] += s[tid + off];
        __syncthreads();
    }
    if (tid < WLANES) g_chunk[c * WLANES + tid] = s[tid];
}

__global__ __launch_bounds__(1024) void prefix_kernel() {
    __shared__ double s[WLANES][NCHUNK];
    int t = threadIdx.x;
#pragma unroll
    for (int l = 0; l < WLANES; l++) s[l][t] = g_chunk[t * WLANES + l];
    __syncthreads();
    for (int off = 1; off < NCHUNK; off <<= 1) {
        double tmp[WLANES];
#pragma unroll
        for (int l = 0; l < WLANES; l++) tmp[l] = (t >= off) ? s[l][t - off] : 0.0;
        __syncthreads();
#pragma unroll
        for (int l = 0; l < WLANES; l++) s[l][t] += tmp[l];
        __syncthreads();
    }
#pragma unroll
    for (int l = 0; l < WLANES; l++) {
        g_pref[t * WLANES + l] = (t > 0) ? s[l][t - 1] : 0.0;
        if (t == NCHUNK - 1) g_lanetot[l] = s[l][t];
    }
}

__global__ void corr_kernel() {
    __shared__ double sp[256];
    int c = blockIdx.x, tid = threadIdx.x;
    int lane  = tid & 3;
    int strip = tid >> 2;
    const float* vbase = g_v + (size_t)c * CHUNK + lane;

    double ssum = 0.0;
#pragma unroll
    for (int j = 0; j < 16; j++)
        ssum += (double)vbase[(size_t)(strip * 16 + j) * 4];
    sp[tid] = ssum;
    __syncthreads();
#pragma unroll
    for (int off = 1; off < 64; off <<= 1) {
        double tmp = (strip >= off) ? sp[(strip - off) * 4 + lane] : 0.0;
        __syncthreads();
        sp[tid] += tmp;
        __syncthreads();
    }
    double run = g_pref[c * WLANES + lane] + ((strip > 0) ? sp[(strip - 1) * 4 + lane] : 0.0);
    __syncthreads();

    double acc = 0.0;
#pragma unroll
    for (int j = 0; j < 16; j++) {
        double v = (double)vbase[(size_t)(strip * 16 + j) * 4];
        double w = run + v;
        if (v > 0.0 && w > 0.0) {
            double u = f32_ulp_of(w);
            acc += rint(v / u) * u - v;
        }
        run += v;
    }

    sp[tid] = acc;
    __syncthreads();
#pragma unroll
    for (int off = 32; off > 0; off >>= 1) {
        if (strip < off) sp[tid] += sp[tid + off * 4];
        __syncthreads();
    }
    if (strip == 0) g_corr[c * WLANES + lane] = sp[lane];
}

__global__ __launch_bounds__(1024) void final_kernel(float* __restrict__ out) {
    __shared__ double s[WLANES][NCHUNK];
    __shared__ float  lf[WLANES];
    int t = threadIdx.x;
#pragma unroll
    for (int l = 0; l < WLANES; l++) s[l][t] = g_corr[t * WLANES + l];
    __syncthreads();
#pragma unroll
    for (int off = 512; off > 0; off >>= 1) {
        if (t < off) {
#pragma unroll
            for (int l = 0; l < WLANES; l++) s[l][t] += s[l][t + off];
        }
        __syncthreads();
    }
    if (t < WLANES) lf[t] = (float)(g_lanetot[t] + s[t][0]);
    __syncthreads();
    if (t == 0) {
        float sum = __fadd_rn(__fadd_rn(lf[0], lf[2]), __fadd_rn(lf[1], lf[3]));
        float m = sum * (1.0f / (float)QELEMS);
        out[LOSS_OFF] = __fadd_rn(m, __fmul_rn(0.25f, m));
    }
}

extern "C" void kernel_launch(void* const* d_in, const int* in_sizes, int n_in,
                              void* d_out, int out_size) {
    const float* in = (const float*)d_in[0];
    const float* cb = (const float*)d_in[1];
    float* out = (float*)d_out;

    cudaFuncSetAttribute(vq3_kernel, cudaFuncAttributeMaxDynamicSharedMemorySize, SMEM_TOTAL);

    prep_kernel<<<4, 256>>>(cb);
    vq3_kernel<<<NVEC / MROWS, MROWS, SMEM_TOTAL>>>(in, cb, out);
    chunk_kernel<<<NCHUNK, 256>>>();
    prefix_kernel<<<1, 1024>>>();
    corr_kernel<<<NCHUNK, 256>>>();
    final_kernel<<<1, 1024>>>(out);
}

// round 8
// speedup vs baseline: 2.5810x; 1.3198x over previous
#include <cuda_runtime.h>
#include <cuda_bf16.h>
#include <cstdint>

#define KCODES   1024
#define DIM      64
#define SPATIAL  16384
#define NVEC     65536
#define QELEMS   4194304

#define NCHUNK   1024
#define CHUNK    4096
#define WLANES   4

#define LOSS_OFF QELEMS
#define IDX_OFF  (QELEMS + 1)

#define MROWS    128
#define NB       128
#define NCHUNKS_B (KCODES / NB)
#define WIN      8e-5f
#define CCAP     48

#define PITCH    144
#define SA_HI    0
#define SA_LO    (SA_HI + MROWS * PITCH)
#define SB_HI    (SA_LO + MROWS * PITCH)
#define SB_LO    (SB_HI + NB * PITCH)
#define S_CBN    (SB_LO + NB * PITCH)
#define S_THR    (S_CBN + NB * 4)
#define S_CNT    (S_THR + MROWS * 4)
#define S_CIDX   (S_CNT + MROWS * 4)
#define S_CP     (S_CIDX + MROWS * CCAP * 2)
#define SMEM_TOTAL (S_CP + MROWS * CCAP * 4)

__device__ float  g_cbn[KCODES];
__device__ __align__(16) __nv_bfloat16 g_cb_hi[KCODES * DIM];
__device__ __align__(16) __nv_bfloat16 g_cb_lo[KCODES * DIM];
__device__ float  g_v[QELEMS];
__device__ double g_chunk[NCHUNK * WLANES];
__device__ double g_pref[NCHUNK * WLANES];
__device__ double g_lanetot[WLANES];
__device__ double g_corr[NCHUNK * WLANES];

__device__ __forceinline__ void mma16816(float* c, const uint32_t* a,
                                         uint32_t b0, uint32_t b1) {
    asm volatile(
        "mma.sync.aligned.m16n8k16.row.col.f32.bf16.bf16.f32 "
        "{%0,%1,%2,%3}, {%4,%5,%6,%7}, {%8,%9}, {%0,%1,%2,%3};"
        : "+f"(c[0]), "+f"(c[1]), "+f"(c[2]), "+f"(c[3])
        : "r"(a[0]), "r"(a[1]), "r"(a[2]), "r"(a[3]), "r"(b0), "r"(b1));
}

// ---------------- prep ----------------
__global__ void prep_kernel(const float* __restrict__ cb) {
    int k = blockIdx.x * blockDim.x + threadIdx.x;
    if (k >= KCODES) return;
    float a = 0.f;
#pragma unroll
    for (int c = 0; c < DIM; c++) {
        float v = cb[k * DIM + c];
        a = __fadd_rn(a, __fmul_rn(v, v));
        __nv_bfloat16 h = __float2bfloat16_rn(v);
        __nv_bfloat16 l = __float2bfloat16_rn(__fsub_rn(v, __bfloat162float(h)));
        g_cb_hi[k * DIM + c] = h;
        g_cb_lo[k * DIM + c] = l;
    }
    g_cbn[k] = a;
}

// ---------------- main: warp-MMA split-bf16 screen + exact recheck ----------------
__global__ __launch_bounds__(MROWS, 2)
void vq3_kernel(const float* __restrict__ in,
                const float* __restrict__ cb,
                float* __restrict__ out)
{
    extern __shared__ char sm[];
    float*  sCbn = (float*)(sm + S_CBN);
    float*  sThr = (float*)(sm + S_THR);
    int*    sCnt = (int*)(sm + S_CNT);
    unsigned short* sCi = (unsigned short*)(sm + S_CIDX);
    float*  sCp  = (float*)(sm + S_CP);

    const int tid  = threadIdx.x;
    const int lane = tid & 31;
    const int g    = lane >> 2;
    const int t4   = lane & 3;
    const int wbase = (tid >> 5) * 32;

    const int n  = blockIdx.x * MROWS + tid;
    const int b  = n >> 14;
    const int sp = n & (SPATIAL - 1);
    const float* xb = in + (size_t)b * DIM * SPATIAL + sp;

    sCnt[tid] = 0;
    {
        char* rh = sm + SA_HI + tid * PITCH;
        char* rl = sm + SA_LO + tid * PITCH;
#pragma unroll
        for (int c = 0; c < DIM; c += 2) {
            float x0 = xb[(size_t)c * SPATIAL];
            float x1 = xb[(size_t)(c + 1) * SPATIAL];
            __nv_bfloat16 h0 = __float2bfloat16_rn(x0);
            __nv_bfloat16 h1 = __float2bfloat16_rn(x1);
            __nv_bfloat16 l0 = __float2bfloat16_rn(__fsub_rn(x0, __bfloat162float(h0)));
            __nv_bfloat16 l1 = __float2bfloat16_rn(__fsub_rn(x1, __bfloat162float(h1)));
            *(uint32_t*)(rh + c * 2) =
                (uint32_t)__bfloat16_as_ushort(h0) | ((uint32_t)__bfloat16_as_ushort(h1) << 16);
            *(uint32_t*)(rl + c * 2) =
                (uint32_t)__bfloat16_as_ushort(l0) | ((uint32_t)__bfloat16_as_ushort(l1) << 16);
        }
    }
    __syncthreads();

    // hoist BOTH A-hi and A-lo fragments (loop-invariant across all chunks)
    uint32_t ahi[2][4][4], alo[2][4][4];
#pragma unroll
    for (int mt = 0; mt < 2; mt++) {
        int r0 = wbase + mt * 16 + g;
#pragma unroll
        for (int ks = 0; ks < 4; ks++) {
            int col = ks * 16 + t4 * 2;
            ahi[mt][ks][0] = *(uint32_t*)(sm + SA_HI + r0 * PITCH + col * 2);
            ahi[mt][ks][1] = *(uint32_t*)(sm + SA_HI + (r0 + 8) * PITCH + col * 2);
            ahi[mt][ks][2] = *(uint32_t*)(sm + SA_HI + r0 * PITCH + (col + 8) * 2);
            ahi[mt][ks][3] = *(uint32_t*)(sm + SA_HI + (r0 + 8) * PITCH + (col + 8) * 2);
            alo[mt][ks][0] = *(uint32_t*)(sm + SA_LO + r0 * PITCH + col * 2);
            alo[mt][ks][1] = *(uint32_t*)(sm + SA_LO + (r0 + 8) * PITCH + col * 2);
            alo[mt][ks][2] = *(uint32_t*)(sm + SA_LO + r0 * PITCH + (col + 8) * 2);
            alo[mt][ks][3] = *(uint32_t*)(sm + SA_LO + (r0 + 8) * PITCH + (col + 8) * 2);
        }
    }

    float rm[4] = {3.4e38f, 3.4e38f, 3.4e38f, 3.4e38f};

#define PUSH(ri, kidx, pv) do { \
        if ((pv) < rm[ri]) rm[ri] = (pv); \
        if ((pv) <= rm[ri] + WIN) { \
            int _r = wbase + (ri) * 8 + g; \
            int _s = atomicAdd(&sCnt[_r], 1); \
            if (_s < CCAP) { sCi[_r * CCAP + _s] = (unsigned short)(kidx); \
                             sCp[_r * CCAP + _s] = (pv); } \
        } \
    } while (0)

    for (int ch = 0; ch < NCHUNKS_B; ch++) {
        __syncthreads();
        {
            const uint4* gh = (const uint4*)(g_cb_hi + (size_t)(ch * NB + tid) * DIM);
            const uint4* gl = (const uint4*)(g_cb_lo + (size_t)(ch * NB + tid) * DIM);
            uint4* dh = (uint4*)(sm + SB_HI + tid * PITCH);
            uint4* dl = (uint4*)(sm + SB_LO + tid * PITCH);
#pragma unroll
            for (int u = 0; u < 8; u++) { dh[u] = gh[u]; dl[u] = gl[u]; }
            sCbn[tid] = g_cbn[ch * NB + tid];
        }
        __syncthreads();

        for (int ng = 0; ng < 4; ng++) {
            float c[4][8];
#pragma unroll
            for (int i = 0; i < 4; i++)
#pragma unroll
                for (int j = 0; j < 8; j++) c[i][j] = 0.f;

#pragma unroll
            for (int ks = 0; ks < 4; ks++) {
#pragma unroll
                for (int nt = 0; nt < 4; nt++) {
                    int nrow = (ng * 4 + nt) * 8 + g;
                    int col  = ks * 16 + t4 * 2;
                    uint32_t bh0 = *(uint32_t*)(sm + SB_HI + nrow * PITCH + col * 2);
                    uint32_t bh1 = *(uint32_t*)(sm + SB_HI + nrow * PITCH + (col + 8) * 2);
                    mma16816(&c[nt][0], ahi[0][ks], bh0, bh1);
                    mma16816(&c[nt][4], ahi[1][ks], bh0, bh1);
                    mma16816(&c[nt][0], alo[0][ks], bh0, bh1);
                    mma16816(&c[nt][4], alo[1][ks], bh0, bh1);
                    uint32_t bl0 = *(uint32_t*)(sm + SB_LO + nrow * PITCH + col * 2);
                    uint32_t bl1 = *(uint32_t*)(sm + SB_LO + nrow * PITCH + (col + 8) * 2);
                    mma16816(&c[nt][0], ahi[0][ks], bl0, bl1);
                    mma16816(&c[nt][4], ahi[1][ks], bl0, bl1);
                }
            }

#pragma unroll
            for (int nt = 0; nt < 4; nt++) {
                int nloc = (ng * 4 + nt) * 8 + t4 * 2;
                int kb   = ch * NB + nloc;
                float cb0 = sCbn[nloc], cb1 = sCbn[nloc + 1];
                float p;
                p = __fmaf_rn(-2.f, c[nt][0], cb0); PUSH(0, kb,     p);
                p = __fmaf_rn(-2.f, c[nt][1], cb1); PUSH(0, kb + 1, p);
                p = __fmaf_rn(-2.f, c[nt][2], cb0); PUSH(1, kb,     p);
                p = __fmaf_rn(-2.f, c[nt][3], cb1); PUSH(1, kb + 1, p);
                p = __fmaf_rn(-2.f, c[nt][4], cb0); PUSH(2, kb,     p);
                p = __fmaf_rn(-2.f, c[nt][5], cb1); PUSH(2, kb + 1, p);
                p = __fmaf_rn(-2.f, c[nt][6], cb0); PUSH(3, kb,     p);
                p = __fmaf_rn(-2.f, c[nt][7], cb1); PUSH(3, kb + 1, p);
            }
        }
    }
#undef PUSH

#pragma unroll
    for (int i = 0; i < 4; i++) {
        float m = rm[i];
        m = fminf(m, __shfl_xor_sync(0xffffffffu, m, 1));
        m = fminf(m, __shfl_xor_sync(0xffffffffu, m, 2));
        if (t4 == 0) sThr[wbase + i * 8 + g] = m + WIN;
    }
    __syncthreads();

    float x[DIM];
    float A = 0.f;
#pragma unroll
    for (int c = 0; c < DIM; c++) {
        x[c] = xb[(size_t)c * SPATIAL];
        A = __fadd_rn(A, __fmul_rn(x[c], x[c]));
    }

    float best = 3.402823466e38f;
    int bestk = KCODES;
    const float thr = sThr[tid];
    const int cnt = sCnt[tid];

#define EVAL_K(kk) do { \
        const float4* cr = (const float4*)(cb + (size_t)(kk) * DIM); \
        float dot = 0.f; \
        _Pragma("unroll") \
        for (int i = 0; i < DIM / 4; i++) { \
            float4 c4 = cr[i]; \
            dot = __fmaf_rn(x[4 * i + 0], c4.x, dot); \
            dot = __fmaf_rn(x[4 * i + 1], c4.y, dot); \
            dot = __fmaf_rn(x[4 * i + 2], c4.z, dot); \
            dot = __fmaf_rn(x[4 * i + 3], c4.w, dot); \
        } \
        float d2 = __fadd_rn(__fsub_rn(A, __fmul_rn(2.0f, dot)), g_cbn[kk]); \
        if (d2 < best || (d2 == best && (kk) < bestk)) { best = d2; bestk = (kk); } \
    } while (0)

    if (cnt > CCAP) {
        for (int k = 0; k < KCODES; k++) EVAL_K(k);
    } else {
        for (int i = 0; i < cnt; i++) {
            if (sCp[tid * CCAP + i] <= thr) {
                int k = sCi[tid * CCAP + i];
                EVAL_K(k);
            }
        }
    }
#undef EVAL_K

    out[IDX_OFF + n] = (float)bestk;

    const float* crow = cb + (size_t)bestk * DIM;
#pragma unroll
    for (int c = 0; c < DIM; c++) {
        float q  = crow[c];
        float df = __fsub_rn(q, x[c]);
        size_t off = ((size_t)(b * DIM + c)) * SPATIAL + sp;
        out[off] = __fadd_rn(x[c], df);
        g_v[off] = __fmul_rn(df, df);
    }
}

// ---------------- loss pipeline ----------------
__global__ void chunk_kernel() {
    __shared__ double s[256];
    int c = blockIdx.x, tid = threadIdx.x;
    double acc = 0.0;
#pragma unroll
    for (int k = 0; k < CHUNK / 256; k++)
        acc += (double)g_v[(size_t)c * CHUNK + tid + k * 256];
    s[tid] = acc;
    __syncthreads();
#pragma unroll
    for (int off = 128; off >= WLANES; off >>= 1) {
        if (tid < off) s[tid] += s[tid + off];
        __syncthreads();
    }
    if (tid < WLANES) g_chunk[c * WLANES + tid] = s[tid];
}

// per-lane exclusive scan over 1024 chunks: 4 warps, warp = lane class
__global__ __launch_bounds__(128) void prefix_kernel() {
    int w = threadIdx.x >> 5;
    int i = threadIdx.x & 31;
    double vals[32], sum = 0.0;
#pragma unroll
    for (int j = 0; j < 32; j++) {
        vals[j] = g_chunk[(i * 32 + j) * WLANES + w];
        sum += vals[j];
    }
    double inc = sum;
#pragma unroll
    for (int off = 1; off < 32; off <<= 1) {
        double t = __shfl_up_sync(0xffffffffu, inc, off);
        if (i >= off) inc += t;
    }
    double run = inc - sum;   // exclusive prefix
#pragma unroll
    for (int j = 0; j < 32; j++) {
        g_pref[(i * 32 + j) * WLANES + w] = run;
        run += vals[j];
    }
    if (i == 31) g_lanetot[w] = run;
}

// per-element fp32 rounding correction — NO fp64 division (u is a power of 2)
__global__ void corr_kernel() {
    __shared__ double sp[256];
    int c = blockIdx.x, tid = threadIdx.x;
    int lane  = tid & 3;
    int strip = tid >> 2;
    const float* vbase = g_v + (size_t)c * CHUNK + lane;

    double ssum = 0.0;
#pragma unroll
    for (int j = 0; j < 16; j++)
        ssum += (double)vbase[(size_t)(strip * 16 + j) * 4];
    sp[tid] = ssum;
    __syncthreads();
#pragma unroll
    for (int off = 1; off < 64; off <<= 1) {
        double tmp = (strip >= off) ? sp[(strip - off) * 4 + lane] : 0.0;
        __syncthreads();
        sp[tid] += tmp;
        __syncthreads();
    }
    double run = g_pref[c * WLANES + lane] + ((strip > 0) ? sp[(strip - 1) * 4 + lane] : 0.0);
    __syncthreads();

    double acc = 0.0;
#pragma unroll
    for (int j = 0; j < 16; j++) {
        float vf = vbase[(size_t)(strip * 16 + j) * 4];
        run += (double)vf;
        int E = (int)(__double_as_longlong(run) >> 52) & 0x7ff;
        if (E >= 920) {
            // u = fp32 ulp of run's binade = 2^(E-1046); exact fp32 arithmetic:
            float u    = __int_as_float((E - 919) << 23);
            float uinv = __int_as_float((1173 - E) << 23);
            float t = vf * uinv;              // exact: t < 2^25 since run >= vf
            float r = rintf(t);
            acc += (double)__fmaf_rn(r, u, -vf);   // exact correction
        }
    }

    sp[tid] = acc;
    __syncthreads();
#pragma unroll
    for (int off = 32; off > 0; off >>= 1) {
        if (strip < off) sp[tid] += sp[tid + off * 4];
        __syncthreads();
    }
    if (strip == 0) g_corr[c * WLANES + lane] = sp[lane];
}

__global__ __launch_bounds__(1024) void final_kernel(float* __restrict__ out) {
    __shared__ double s[WLANES][NCHUNK];
    __shared__ float  lf[WLANES];
    int t = threadIdx.x;
#pragma unroll
    for (int l = 0; l < WLANES; l++) s[l][t] = g_corr[t * WLANES + l];
    __syncthreads();
#pragma unroll
    for (int off = 512; off > 0; off >>= 1) {
        if (t < off) {
#pragma unroll
            for (int l = 0; l < WLANES; l++) s[l][t] += s[l][t + off];
        }
        __syncthreads();
    }
    if (t < WLANES) lf[t] = (float)(g_lanetot[t] + s[t][0]);
    __syncthreads();
    if (t == 0) {
        float sum = __fadd_rn(__fadd_rn(lf[0], lf[2]), __fadd_rn(lf[1], lf[3]));
        float m = sum * (1.0f / (float)QELEMS);
        out[LOSS_OFF] = __fadd_rn(m, __fmul_rn(0.25f, m));
    }
}

extern "C" void kernel_launch(void* const* d_in, const int* in_sizes, int n_in,
                              void* d_out, int out_size) {
    const float* in = (const float*)d_in[0];
    const float* cb = (const float*)d_in[1];
    float* out = (float*)d_out;

    cudaFuncSetAttribute(vq3_kernel, cudaFuncAttributeMaxDynamicSharedMemorySize, SMEM_TOTAL);

    prep_kernel<<<4, 256>>>(cb);
    vq3_kernel<<<NVEC / MROWS, MROWS, SMEM_TOTAL>>>(in, cb, out);
    chunk_kernel<<<NCHUNK, 256>>>();
    prefix_kernel<<<1, 128>>>();
    corr_kernel<<<NCHUNK, 256>>>();
    final_kernel<<<1, 1024>>>(out);
}